// round 4
// baseline (speedup 1.0000x reference)
#include <cuda_runtime.h>
#include <math.h>

#define NN 50000
#define NE 800000
#define DD 128
#define NG 16

#define NEG_INF_BITS 0xFF800000u

#define SCAN_B 256
#define NBLK ((NN + SCAN_B - 1) / SCAN_B)   // 196

// Scratch (no cudaMalloc). float4 for guaranteed 16B alignment.
__device__ float4 g_bufA4[NN * DD / 4];
__device__ float4 g_bufB4[NN * DD / 4];
__device__ float4 g_agg4[NN * DD / 4];
__device__ float g_xg[NG * DD];
__device__ int g_i64;
// CSR (dst-sorted adjacency)
__device__ int g_deg[NN];
__device__ int g_off[NN + 1];
__device__ int g_cur[NN];
__device__ int g_csr[NE];
__device__ int g_part[NBLK];
__device__ int g_poff[NBLK];

__device__ __forceinline__ const float* sel_in(int sel, const float* x, const float* dout) {
    return sel == 0 ? x : sel == 1 ? (const float*)g_bufA4 : sel == 2 ? (const float*)g_bufB4 : dout;
}
__device__ __forceinline__ float* sel_out(int sel, float* dout) {
    return sel == 1 ? (float*)g_bufA4 : sel == 2 ? (float*)g_bufB4 : dout;
}

__device__ __forceinline__ void atomicMaxF(float* a, float v) {
    if (v >= 0.f) atomicMax((int*)a, __float_as_int(v));
    else          atomicMin((unsigned int*)a, __float_as_uint(v));
}

__device__ __forceinline__ float fixneg(float v) {
    return (__float_as_uint(v) == NEG_INF_BITS) ? 0.f : v;
}

// ---------------- dtype detection ----------------
__global__ void k_detect(const int* __restrict__ ei32) {
    int mode = 1;
    for (int i = 0; i < 64; ++i) {
        if (ei32[2 * i + 1] != 0) { mode = 0; break; }
    }
    g_i64 = mode;
}

__device__ __forceinline__ int idx_at(const int* p32, int i) {
    return g_i64 ? p32[2 * i] : p32[i];
}

// ---------------- CSR build ----------------
__global__ void k_zero_deg() {
    int i = blockIdx.x * blockDim.x + threadIdx.x;
    if (i < NN) g_deg[i] = 0;
}

__global__ void k_count(const int* __restrict__ ei32) {
    int e = blockIdx.x * blockDim.x + threadIdx.x;
    if (e < NE) atomicAdd(&g_deg[idx_at(ei32, NE + e)], 1);
}

// phase 1: per-block partial sums
__global__ void k_partial() {
    __shared__ int sh[SCAN_B];
    int idx = blockIdx.x * SCAN_B + threadIdx.x;
    int v = (idx < NN) ? g_deg[idx] : 0;
    sh[threadIdx.x] = v;
    __syncthreads();
    for (int off = SCAN_B / 2; off > 0; off >>= 1) {
        if (threadIdx.x < off) sh[threadIdx.x] += sh[threadIdx.x + off];
        __syncthreads();
    }
    if (threadIdx.x == 0) g_part[blockIdx.x] = sh[0];
}

// phase 2: single-block exclusive scan of NBLK partials
__global__ void k_scanpart() {
    __shared__ int sh[SCAN_B];
    int t = threadIdx.x;
    int v = (t < NBLK) ? g_part[t] : 0;
    sh[t] = v;
    __syncthreads();
    for (int off = 1; off < SCAN_B; off <<= 1) {
        int u = (t >= off) ? sh[t - off] : 0;
        __syncthreads();
        sh[t] += u;
        __syncthreads();
    }
    if (t < NBLK) g_poff[t] = sh[t] - v;  // exclusive
}

// phase 3: per-block exclusive scan + base, write offsets
__global__ void k_offsets() {
    __shared__ int sh[SCAN_B];
    int t = threadIdx.x;
    int idx = blockIdx.x * SCAN_B + t;
    int d = (idx < NN) ? g_deg[idx] : 0;
    sh[t] = d;
    __syncthreads();
    for (int off = 1; off < SCAN_B; off <<= 1) {
        int u = (t >= off) ? sh[t - off] : 0;
        __syncthreads();
        sh[t] += u;
        __syncthreads();
    }
    if (idx < NN) {
        int o = g_poff[blockIdx.x] + sh[t] - d;
        g_off[idx] = o;
        g_cur[idx] = o;
        if (idx == NN - 1) g_off[NN] = o + d;
    }
}

__global__ void k_fill(const int* __restrict__ ei32) {
    int e = blockIdx.x * blockDim.x + threadIdx.x;
    if (e < NE) {
        int d = idx_at(ei32, NE + e);
        int s = idx_at(ei32, e);
        int pos = atomicAdd(&g_cur[d], 1);
        g_csr[pos] = s;
    }
}

// ---------------- aggregation: warp-per-node gather-max ----------------
__global__ void k_agg(int insel, const float* __restrict__ x, const float* __restrict__ doutc) {
    const float* h = sel_in(insel, x, doutc);
    const int warp = (blockIdx.x * blockDim.x + threadIdx.x) >> 5;
    const int lane = threadIdx.x & 31;
    if (warp >= NN) return;
    const int e0 = g_off[warp];
    const int e1 = g_off[warp + 1];
    float4 m = make_float4(0.f, 0.f, 0.f, 0.f);
    if (e1 > e0) {
        const float ni = __uint_as_float(NEG_INF_BITS);
        m = make_float4(ni, ni, ni, ni);
        int e = e0;
        for (; e + 3 < e1; e += 4) {
            int s0 = g_csr[e], s1 = g_csr[e + 1], s2 = g_csr[e + 2], s3 = g_csr[e + 3];
            float4 v0 = ((const float4*)h)[(size_t)s0 * 32 + lane];
            float4 v1 = ((const float4*)h)[(size_t)s1 * 32 + lane];
            float4 v2 = ((const float4*)h)[(size_t)s2 * 32 + lane];
            float4 v3 = ((const float4*)h)[(size_t)s3 * 32 + lane];
            m.x = fmaxf(fmaxf(m.x, v0.x), fmaxf(v1.x, fmaxf(v2.x, v3.x)));
            m.y = fmaxf(fmaxf(m.y, v0.y), fmaxf(v1.y, fmaxf(v2.y, v3.y)));
            m.z = fmaxf(fmaxf(m.z, v0.z), fmaxf(v1.z, fmaxf(v2.z, v3.z)));
            m.w = fmaxf(fmaxf(m.w, v0.w), fmaxf(v1.w, fmaxf(v2.w, v3.w)));
        }
        for (; e < e1; ++e) {
            int s0 = g_csr[e];
            float4 v0 = ((const float4*)h)[(size_t)s0 * 32 + lane];
            m.x = fmaxf(m.x, v0.x); m.y = fmaxf(m.y, v0.y);
            m.z = fmaxf(m.z, v0.z); m.w = fmaxf(m.w, v0.w);
        }
    }
    g_agg4[(size_t)warp * 32 + lane] = m;
}

// ---------------- fused concat-GEMM + bias + leaky + residual ----------------
// Block tile 128x128, thread tile 8x8, BK=16, 256 threads.
__global__ void __launch_bounds__(256, 2)
k_gemm(int insel, int outsel, const float* __restrict__ x, float* __restrict__ dout,
       const float* __restrict__ w, const float* __restrict__ b, int addskip) {
    const float* h = sel_in(insel, x, dout);
    float* out = sel_out(outsel, dout);

    __shared__ float As[16][128];
    __shared__ float Ws[16][128];

    const int tid = threadIdx.x;
    const int tx = tid & 15;        // col group: cols tx*8..tx*8+7
    const int ty = tid >> 4;        // row group: rows ty*8..ty*8+7
    const int m0 = blockIdx.x * 128;

    const int arow = tid >> 1;          // 0..127
    const int acg = (tid & 1) * 8;      // 0 or 8

    float acc[8][8];
#pragma unroll
    for (int i = 0; i < 8; ++i)
#pragma unroll
        for (int j = 0; j < 8; ++j) acc[i][j] = 0.f;

    for (int kt = 0; kt < 16; ++kt) {
        const float* A = (kt < 8) ? h : (const float*)g_agg4;
        const int kloc = (kt & 7) * 16 + acg;

        float4 av0 = make_float4(0.f, 0.f, 0.f, 0.f);
        float4 av1 = make_float4(0.f, 0.f, 0.f, 0.f);
        const int gr = m0 + arow;
        if (gr < NN) {
            av0 = *(const float4*)(A + (size_t)gr * DD + kloc);
            av1 = *(const float4*)(A + (size_t)gr * DD + kloc + 4);
        }
        As[acg + 0][arow] = av0.x;
        As[acg + 1][arow] = av0.y;
        As[acg + 2][arow] = av0.z;
        As[acg + 3][arow] = av0.w;
        As[acg + 4][arow] = av1.x;
        As[acg + 5][arow] = av1.y;
        As[acg + 6][arow] = av1.z;
        As[acg + 7][arow] = av1.w;

        {
            const int wr = tid >> 4;            // 0..15
            const int wc = (tid & 15) * 8;      // 0,8,...,120
            const float* wp = w + (size_t)(kt * 16 + wr) * DD + wc;
            *(float4*)&Ws[wr][wc] = *(const float4*)wp;
            *(float4*)&Ws[wr][wc + 4] = *(const float4*)(wp + 4);
        }
        __syncthreads();

#pragma unroll
        for (int kk = 0; kk < 16; ++kk) {
            float a[8], wv[8];
            *(float4*)&a[0] = *(const float4*)&As[kk][ty * 8];
            *(float4*)&a[4] = *(const float4*)&As[kk][ty * 8 + 4];
            *(float4*)&wv[0] = *(const float4*)&Ws[kk][tx * 8];
            *(float4*)&wv[4] = *(const float4*)&Ws[kk][tx * 8 + 4];
#pragma unroll
            for (int i = 0; i < 8; ++i)
#pragma unroll
                for (int j = 0; j < 8; ++j)
                    acc[i][j] = fmaf(a[i], wv[j], acc[i][j]);
        }
        __syncthreads();
    }

    float bias[8];
    *(float4*)&bias[0] = *(const float4*)(b + tx * 8);
    *(float4*)&bias[4] = *(const float4*)(b + tx * 8 + 4);

#pragma unroll
    for (int i = 0; i < 8; ++i) {
        int gr = m0 + ty * 8 + i;
        if (gr < NN) {
            float v[8];
#pragma unroll
            for (int j = 0; j < 8; ++j) {
                float t = acc[i][j] + bias[j];
                v[j] = t > 0.f ? t : 0.01f * t;
            }
            if (addskip) {
                float4 h0 = *(const float4*)(h + (size_t)gr * DD + tx * 8);
                float4 h1 = *(const float4*)(h + (size_t)gr * DD + tx * 8 + 4);
                v[0] += h0.x; v[1] += h0.y; v[2] += h0.z; v[3] += h0.w;
                v[4] += h1.x; v[5] += h1.y; v[6] += h1.z; v[7] += h1.w;
            }
            *(float4*)(out + (size_t)gr * DD + tx * 8) = *(float4*)&v[0];
            *(float4*)(out + (size_t)gr * DD + tx * 8 + 4) = *(float4*)&v[4];
        }
    }
}

// ---------------- global pool ----------------
__global__ void k_init_xg() {
    unsigned int i = blockIdx.x * blockDim.x + threadIdx.x;
    if (i < NG * DD) ((unsigned int*)g_xg)[i] = NEG_INF_BITS;
}

__device__ __forceinline__ int lower_bound_b(const int* b32, int n, int v) {
    int lo = 0, hi = n;
    while (lo < hi) {
        int mid = (lo + hi) >> 1;
        if (idx_at(b32, mid) < v) lo = mid + 1;
        else hi = mid;
    }
    return lo;
}

__global__ void k_segmax(const float* __restrict__ h, const int* __restrict__ batch32) {
    const int g = blockIdx.x;
    const int chunk = blockIdx.y;
    const int d = threadIdx.x;
    int start = lower_bound_b(batch32, NN, g);
    int end = lower_bound_b(batch32, NN, g + 1);
    int len = end - start;
    if (len <= 0) return;
    int per = (len + gridDim.y - 1) / gridDim.y;
    int s = start + chunk * per;
    int e = s + per;
    if (e > end) e = end;
    if (s >= e) return;
    float m = __uint_as_float(NEG_INF_BITS);
    for (int r = s; r < e; ++r) m = fmaxf(m, h[(size_t)r * DD + d]);
    atomicMaxF(&g_xg[g * DD + d], m);
}

__global__ void k_combine(float* __restrict__ dout, const float* __restrict__ wg,
                          const float* __restrict__ bg, int out_size) {
    const int g = blockIdx.x;
    const int n = threadIdx.x;
    float acc = bg[n];
    for (int k = 0; k < DD; ++k) {
        float xv = fixneg(g_xg[g * DD + k]);
        acc = fmaf(xv, wg[(size_t)k * DD + n], acc);
    }
    acc = acc > 0.f ? acc : 0.01f * acc;
    long long oi = (long long)NN * DD + g * DD + n;
    if (oi < (long long)out_size) dout[oi] = acc;
}

// ---------------- launch ----------------
extern "C" void kernel_launch(void* const* d_in, const int* in_sizes, int n_in,
                              void* d_out, int out_size) {
    const float* x = (const float*)d_in[0];
    const int* ei32 = (const int*)d_in[1];
    const int* batch32 = (const int*)d_in[2];
    const int wb = n_in - 10;  // w0,b0,w1,b1,w2,b2,w3,b3,wg,bg
    float* dout = (float*)d_out;

    k_detect<<<1, 1>>>(ei32);

    // CSR build
    k_zero_deg<<<(NN + 255) / 256, 256>>>();
    k_count<<<(NE + 255) / 256, 256>>>(ei32);
    k_partial<<<NBLK, SCAN_B>>>();
    k_scanpart<<<1, SCAN_B>>>();
    k_offsets<<<NBLK, SCAN_B>>>();
    k_fill<<<(NE + 255) / 256, 256>>>(ei32);

    int insel = 0;
    for (int s = 0; s < 4; ++s) {
        int outsel = (s == 3) ? 3 : ((s % 2 == 0) ? 1 : 2);
        k_agg<<<(NN * 32 + 255) / 256, 256>>>(insel, x, dout);
        k_gemm<<<(NN + 127) / 128, 256>>>(insel, outsel, x, dout,
                                          (const float*)d_in[wb + 2 * s],
                                          (const float*)d_in[wb + 2 * s + 1],
                                          s > 0 ? 1 : 0);
        insel = outsel;
    }

    k_init_xg<<<8, 256>>>();
    dim3 gsg(NG, 32);
    k_segmax<<<gsg, 128>>>(dout, batch32);
    k_combine<<<NG, 128>>>(dout, (const float*)d_in[wb + 8], (const float*)d_in[wb + 9], out_size);
}

// round 5
// speedup vs baseline: 1.2471x; 1.2471x over previous
#include <cuda_runtime.h>
#include <math.h>

#define NN 50000
#define NE 800000
#define DD 128
#define NG 16

#define NEG_INF_BITS 0xFF800000u

#define SCAN_B 256
#define NBLK ((NN + SCAN_B - 1) / SCAN_B)   // 196

// Scratch (no cudaMalloc). float4 for guaranteed 16B alignment.
__device__ float4 g_bufA4[NN * DD / 4];
__device__ float4 g_bufB4[NN * DD / 4];
__device__ float4 g_agg4[NN * DD / 4];
__device__ float g_xg[NG * DD];
__device__ int g_i64;
// CSR (dst-sorted adjacency)
__device__ int g_deg[NN];
__device__ int g_off[NN + 1];
__device__ int g_cur[NN];
__device__ int g_csr[NE];
__device__ int g_part[NBLK];
__device__ int g_poff[NBLK];

__device__ __forceinline__ const float* sel_in(int sel, const float* x, const float* dout) {
    return sel == 0 ? x : sel == 1 ? (const float*)g_bufA4 : sel == 2 ? (const float*)g_bufB4 : dout;
}
__device__ __forceinline__ float* sel_out(int sel, float* dout) {
    return sel == 1 ? (float*)g_bufA4 : sel == 2 ? (float*)g_bufB4 : dout;
}

__device__ __forceinline__ void atomicMaxF(float* a, float v) {
    if (v >= 0.f) atomicMax((int*)a, __float_as_int(v));
    else          atomicMin((unsigned int*)a, __float_as_uint(v));
}

__device__ __forceinline__ float fixneg(float v) {
    return (__float_as_uint(v) == NEG_INF_BITS) ? 0.f : v;
}

// ---------------- dtype detection ----------------
__global__ void k_detect(const int* __restrict__ ei32) {
    int mode = 1;
    for (int i = 0; i < 64; ++i) {
        if (ei32[2 * i + 1] != 0) { mode = 0; break; }
    }
    g_i64 = mode;
}

__device__ __forceinline__ int idx_at(const int* p32, int i) {
    return g_i64 ? p32[2 * i] : p32[i];
}

// ---------------- CSR build ----------------
__global__ void k_zero_deg() {
    int i = blockIdx.x * blockDim.x + threadIdx.x;
    if (i < NN) g_deg[i] = 0;
}

__global__ void k_count(const int* __restrict__ ei32) {
    int e = blockIdx.x * blockDim.x + threadIdx.x;
    if (e < NE) atomicAdd(&g_deg[idx_at(ei32, NE + e)], 1);
}

__global__ void k_partial() {
    __shared__ int sh[SCAN_B];
    int idx = blockIdx.x * SCAN_B + threadIdx.x;
    int v = (idx < NN) ? g_deg[idx] : 0;
    sh[threadIdx.x] = v;
    __syncthreads();
    for (int off = SCAN_B / 2; off > 0; off >>= 1) {
        if (threadIdx.x < off) sh[threadIdx.x] += sh[threadIdx.x + off];
        __syncthreads();
    }
    if (threadIdx.x == 0) g_part[blockIdx.x] = sh[0];
}

__global__ void k_scanpart() {
    __shared__ int sh[SCAN_B];
    int t = threadIdx.x;
    int v = (t < NBLK) ? g_part[t] : 0;
    sh[t] = v;
    __syncthreads();
    for (int off = 1; off < SCAN_B; off <<= 1) {
        int u = (t >= off) ? sh[t - off] : 0;
        __syncthreads();
        sh[t] += u;
        __syncthreads();
    }
    if (t < NBLK) g_poff[t] = sh[t] - v;  // exclusive
}

__global__ void k_offsets() {
    __shared__ int sh[SCAN_B];
    int t = threadIdx.x;
    int idx = blockIdx.x * SCAN_B + t;
    int d = (idx < NN) ? g_deg[idx] : 0;
    sh[t] = d;
    __syncthreads();
    for (int off = 1; off < SCAN_B; off <<= 1) {
        int u = (t >= off) ? sh[t - off] : 0;
        __syncthreads();
        sh[t] += u;
        __syncthreads();
    }
    if (idx < NN) {
        int o = g_poff[blockIdx.x] + sh[t] - d;
        g_off[idx] = o;
        g_cur[idx] = o;
        if (idx == NN - 1) g_off[NN] = o + d;
    }
}

__global__ void k_fill(const int* __restrict__ ei32) {
    int e = blockIdx.x * blockDim.x + threadIdx.x;
    if (e < NE) {
        int d = idx_at(ei32, NE + e);
        int s = idx_at(ei32, e);
        int pos = atomicAdd(&g_cur[d], 1);
        g_csr[pos] = s;
    }
}

// ---------------- aggregation: warp-per-node gather-max ----------------
__global__ void k_agg(int insel, const float* __restrict__ x, const float* __restrict__ doutc) {
    const float* h = sel_in(insel, x, doutc);
    const int warp = (blockIdx.x * blockDim.x + threadIdx.x) >> 5;
    const int lane = threadIdx.x & 31;
    if (warp >= NN) return;
    const int e0 = g_off[warp];
    const int e1 = g_off[warp + 1];
    float4 m = make_float4(0.f, 0.f, 0.f, 0.f);
    if (e1 > e0) {
        const float ni = __uint_as_float(NEG_INF_BITS);
        m = make_float4(ni, ni, ni, ni);
        int e = e0;
        for (; e + 3 < e1; e += 4) {
            int s0 = g_csr[e], s1 = g_csr[e + 1], s2 = g_csr[e + 2], s3 = g_csr[e + 3];
            float4 v0 = ((const float4*)h)[(size_t)s0 * 32 + lane];
            float4 v1 = ((const float4*)h)[(size_t)s1 * 32 + lane];
            float4 v2 = ((const float4*)h)[(size_t)s2 * 32 + lane];
            float4 v3 = ((const float4*)h)[(size_t)s3 * 32 + lane];
            m.x = fmaxf(fmaxf(m.x, v0.x), fmaxf(v1.x, fmaxf(v2.x, v3.x)));
            m.y = fmaxf(fmaxf(m.y, v0.y), fmaxf(v1.y, fmaxf(v2.y, v3.y)));
            m.z = fmaxf(fmaxf(m.z, v0.z), fmaxf(v1.z, fmaxf(v2.z, v3.z)));
            m.w = fmaxf(fmaxf(m.w, v0.w), fmaxf(v1.w, fmaxf(v2.w, v3.w)));
        }
        for (; e < e1; ++e) {
            int s0 = g_csr[e];
            float4 v0 = ((const float4*)h)[(size_t)s0 * 32 + lane];
            m.x = fmaxf(m.x, v0.x); m.y = fmaxf(m.y, v0.y);
            m.z = fmaxf(m.z, v0.z); m.w = fmaxf(m.w, v0.w);
        }
    }
    g_agg4[(size_t)warp * 32 + lane] = m;
}

// ---------------- fused concat-GEMM + bias + leaky + residual ----------------
// Block 64x128, thread tile 8x4, BK=16 (R3 shape), double-buffered smem with
// register prefetch: one sync per k-tile.
__global__ void k_gemm(int insel, int outsel, const float* __restrict__ x, float* __restrict__ dout,
                       const float* __restrict__ w, const float* __restrict__ b, int addskip) {
    const float* h = sel_in(insel, x, dout);
    float* out = sel_out(outsel, dout);

    __shared__ float As[2][16][64];
    __shared__ float Ws[2][16][128];

    const int tid = threadIdx.x;
    const int tx = tid & 31;
    const int ty = tid >> 5;
    const int m0 = blockIdx.x * 64;

    const int arow = tid >> 2;       // 0..63
    const int acg = (tid & 3) * 4;   // 0,4,8,12
    const int wr = tid >> 5;         // 0..7 (x2 halves)
    const int wc = (tid & 31) << 2;

    float acc[8][4];
#pragma unroll
    for (int i = 0; i < 8; ++i)
#pragma unroll
        for (int j = 0; j < 4; ++j) acc[i][j] = 0.f;

    const int gr = m0 + arow;

    // prefetch tile 0
    float4 av;
    float4 wv0, wv1;
    {
        const float* A = h;
        av = make_float4(0.f, 0.f, 0.f, 0.f);
        if (gr < NN) av = *(const float4*)(A + (size_t)gr * DD + acg);
        const float* wp = w + (size_t)wr * DD + wc;
        wv0 = *(const float4*)wp;
        wv1 = *(const float4*)(wp + (size_t)8 * DD);
    }

    for (int kt = 0; kt < 16; ++kt) {
        const int buf = kt & 1;
        // store prefetched regs to smem
        As[buf][acg + 0][arow] = av.x;
        As[buf][acg + 1][arow] = av.y;
        As[buf][acg + 2][arow] = av.z;
        As[buf][acg + 3][arow] = av.w;
        *(float4*)&Ws[buf][wr][wc] = wv0;
        *(float4*)&Ws[buf][wr + 8][wc] = wv1;
        __syncthreads();

        // prefetch tile kt+1
        if (kt < 15) {
            const int nt = kt + 1;
            const float* A = (nt < 8) ? h : (const float*)g_agg4;
            const int kloc = (nt & 7) * 16 + acg;
            av = make_float4(0.f, 0.f, 0.f, 0.f);
            if (gr < NN) av = *(const float4*)(A + (size_t)gr * DD + kloc);
            const float* wp = w + (size_t)(nt * 16 + wr) * DD + wc;
            wv0 = *(const float4*)wp;
            wv1 = *(const float4*)(wp + (size_t)8 * DD);
        }

        // compute tile kt
#pragma unroll
        for (int kk = 0; kk < 16; ++kk) {
            float a[8];
#pragma unroll
            for (int i = 0; i < 8; ++i) a[i] = As[buf][kk][ty * 8 + i];
            float4 wv = *(const float4*)&Ws[buf][kk][tx * 4];
#pragma unroll
            for (int i = 0; i < 8; ++i) {
                acc[i][0] = fmaf(a[i], wv.x, acc[i][0]);
                acc[i][1] = fmaf(a[i], wv.y, acc[i][1]);
                acc[i][2] = fmaf(a[i], wv.z, acc[i][2]);
                acc[i][3] = fmaf(a[i], wv.w, acc[i][3]);
            }
        }
        __syncthreads();
    }

    const float4 bias = *(const float4*)(b + tx * 4);
#pragma unroll
    for (int i = 0; i < 8; ++i) {
        int grr = m0 + ty * 8 + i;
        if (grr < NN) {
            float4 v;
            v.x = acc[i][0] + bias.x;
            v.y = acc[i][1] + bias.y;
            v.z = acc[i][2] + bias.z;
            v.w = acc[i][3] + bias.w;
            v.x = v.x > 0.f ? v.x : 0.01f * v.x;
            v.y = v.y > 0.f ? v.y : 0.01f * v.y;
            v.z = v.z > 0.f ? v.z : 0.01f * v.z;
            v.w = v.w > 0.f ? v.w : 0.01f * v.w;
            if (addskip) {
                float4 hv = *(const float4*)(h + (size_t)grr * DD + tx * 4);
                v.x += hv.x; v.y += hv.y; v.z += hv.z; v.w += hv.w;
            }
            *(float4*)(out + (size_t)grr * DD + tx * 4) = v;
        }
    }
}

// ---------------- global pool ----------------
__global__ void k_init_xg() {
    unsigned int i = blockIdx.x * blockDim.x + threadIdx.x;
    if (i < NG * DD) ((unsigned int*)g_xg)[i] = NEG_INF_BITS;
}

__device__ __forceinline__ int lower_bound_b(const int* b32, int n, int v) {
    int lo = 0, hi = n;
    while (lo < hi) {
        int mid = (lo + hi) >> 1;
        if (idx_at(b32, mid) < v) lo = mid + 1;
        else hi = mid;
    }
    return lo;
}

__global__ void k_segmax(const float* __restrict__ h, const int* __restrict__ batch32) {
    const int g = blockIdx.x;
    const int chunk = blockIdx.y;
    const int d = threadIdx.x;
    int start = lower_bound_b(batch32, NN, g);
    int end = lower_bound_b(batch32, NN, g + 1);
    int len = end - start;
    if (len <= 0) return;
    int per = (len + gridDim.y - 1) / gridDim.y;
    int s = start + chunk * per;
    int e = s + per;
    if (e > end) e = end;
    if (s >= e) return;
    float m = __uint_as_float(NEG_INF_BITS);
    for (int r = s; r < e; ++r) m = fmaxf(m, h[(size_t)r * DD + d]);
    atomicMaxF(&g_xg[g * DD + d], m);
}

__global__ void k_combine(float* __restrict__ dout, const float* __restrict__ wg,
                          const float* __restrict__ bg, int out_size) {
    const int g = blockIdx.x;
    const int n = threadIdx.x;
    float acc = bg[n];
    for (int k = 0; k < DD; ++k) {
        float xv = fixneg(g_xg[g * DD + k]);
        acc = fmaf(xv, wg[(size_t)k * DD + n], acc);
    }
    acc = acc > 0.f ? acc : 0.01f * acc;
    long long oi = (long long)NN * DD + g * DD + n;
    if (oi < (long long)out_size) dout[oi] = acc;
}

// ---------------- launch ----------------
extern "C" void kernel_launch(void* const* d_in, const int* in_sizes, int n_in,
                              void* d_out, int out_size) {
    const float* x = (const float*)d_in[0];
    const int* ei32 = (const int*)d_in[1];
    const int* batch32 = (const int*)d_in[2];
    const int wb = n_in - 10;  // w0,b0,w1,b1,w2,b2,w3,b3,wg,bg
    float* dout = (float*)d_out;

    k_detect<<<1, 1>>>(ei32);

    // CSR build
    k_zero_deg<<<(NN + 255) / 256, 256>>>();
    k_count<<<(NE + 255) / 256, 256>>>(ei32);
    k_partial<<<NBLK, SCAN_B>>>();
    k_scanpart<<<1, SCAN_B>>>();
    k_offsets<<<NBLK, SCAN_B>>>();
    k_fill<<<(NE + 255) / 256, 256>>>(ei32);

    int insel = 0;
    for (int s = 0; s < 4; ++s) {
        int outsel = (s == 3) ? 3 : ((s % 2 == 0) ? 1 : 2);
        k_agg<<<(NN * 32 + 255) / 256, 256>>>(insel, x, dout);
        k_gemm<<<(NN + 63) / 64, 256>>>(insel, outsel, x, dout,
                                        (const float*)d_in[wb + 2 * s],
                                        (const float*)d_in[wb + 2 * s + 1],
                                        s > 0 ? 1 : 0);
        insel = outsel;
    }

    k_init_xg<<<8, 256>>>();
    dim3 gsg(NG, 32);
    k_segmax<<<gsg, 128>>>(dout, batch32);
    k_combine<<<NG, 128>>>(dout, (const float*)d_in[wb + 8], (const float*)d_in[wb + 9], out_size);
}